// round 8
// baseline (speedup 1.0000x reference)
#include <cuda_runtime.h>
#include <cuda_bf16.h>
#include <math.h>
#include <stdint.h>

// ---------------- shapes ----------------
#define B_    8
#define L_    1024
#define F_    1024
#define H_    256
#define NH_   8
#define LBL_  4766
#define ROWS_ (B_*L_)      // 8192
#define OH_   (NH_*H_)     // 2048

// ---------------- scratch ----------------
__device__ float g_x1[ROWS_*H_];
__device__ float g_x2[ROWS_*H_];
__device__ float g_stats[ROWS_*2];
__device__ float g_att[B_*NH_*L_];
__device__ float g_part[B_*16*NH_*H_];
__device__ float g_h[B_*OH_];
__device__ float g_h1[B_*OH_];
__device__ float g_p[B_*LBL_];
__device__ float g_op1[16*8*OH_];
__device__ float g_op2[16*8*LBL_];

// ---------------- helpers ----------------
__device__ __forceinline__ float leaky(float v) { return v >= 0.f ? v : 0.01f * v; }
__device__ __forceinline__ unsigned short f2bf(float f) {
    return __bfloat16_as_ushort(__float2bfloat16_rn(f));
}
__device__ __forceinline__ float bf2f(unsigned short u) {
    return __bfloat162float(__ushort_as_bfloat16(u));
}

__device__ __forceinline__ void mma_bf16(float* d, const uint32_t* a, const uint32_t* b) {
    asm volatile(
        "mma.sync.aligned.m16n8k16.row.col.f32.bf16.bf16.f32 "
        "{%0,%1,%2,%3}, {%4,%5,%6,%7}, {%8,%9}, {%0,%1,%2,%3};"
        : "+f"(d[0]), "+f"(d[1]), "+f"(d[2]), "+f"(d[3])
        : "r"(a[0]), "r"(a[1]), "r"(a[2]), "r"(a[3]), "r"(b[0]), "r"(b[1]));
}

__device__ __forceinline__ void block_reduce2(float& a, float& b, float* s) {
    int t = threadIdx.x;
    s[t] = a; s[256 + t] = b; __syncthreads();
    #pragma unroll
    for (int st = 128; st > 0; st >>= 1) {
        if (t < st) { s[t] += s[t + st]; s[256 + t] += s[256 + t + st]; }
        __syncthreads();
    }
    a = s[0]; b = s[256];
    __syncthreads();
}

// ---------------- per-row LN stats ----------------
template<int NF>
__global__ __launch_bounds__(256) void rowstat_kernel(const float* __restrict__ in,
                                                      float* __restrict__ stats) {
    constexpr int VPT = NF / 256;
    __shared__ float s[512];
    const float* row = in + (size_t)blockIdx.x * NF;
    float sum = 0.f, sq = 0.f;
    #pragma unroll
    for (int i = 0; i < VPT; i++) {
        float v = row[threadIdx.x + i * 256];
        sum += v; sq += v * v;
    }
    block_reduce2(sum, sq, s);
    if (threadIdx.x == 0) {
        float m   = sum * (1.0f / NF);
        float var = sq  * (1.0f / NF) - m * m;
        stats[2 * blockIdx.x]     = m;
        stats[2 * blockIdx.x + 1] = rsqrtf(var + 1e-6f);
    }
}

// ---------------- full LayerNorm ----------------
template<int NF>
__global__ __launch_bounds__(256) void ln_kernel(const float* __restrict__ in,
                                                 float* __restrict__ out,
                                                 const float* __restrict__ g,
                                                 const float* __restrict__ b) {
    constexpr int VPT = NF / 256;
    __shared__ float s[512];
    const float* row = in + (size_t)blockIdx.x * NF;
    float v[VPT];
    float sum = 0.f, sq = 0.f;
    #pragma unroll
    for (int i = 0; i < VPT; i++) {
        v[i] = row[threadIdx.x + i * 256];
        sum += v[i]; sq += v[i] * v[i];
    }
    block_reduce2(sum, sq, s);
    float m   = sum * (1.0f / NF);
    float var = sq  * (1.0f / NF) - m * m;
    float inv = rsqrtf(var + 1e-6f);
    float* orow = out + (size_t)blockIdx.x * NF;
    #pragma unroll
    for (int i = 0; i < VPT; i++) {
        int c = threadIdx.x + i * 256;
        orow[c] = (v[i] - m) * inv * g[c] + b[c];
    }
}

// ============ HMMA bf16 GEMM: C = leaky( LN(A) @ W + bias ) ===================
// 3-term hi/lo split into fp32 accumulators via mma.sync m16n8k16.
// Tile 128x128, BK=64. 8 warps (2x4), warp tile 64x32.
// Smem: Ahi/Alo [128][72] bf16 row-major [m][k]; Bhi/Blo [128][72] bf16 [n][k].
#define AP   72                      // bf16 pitch (pad 64->72): conflict-free frags
#define ATB  (128*AP*2)              // 18432 bytes per tile
#define GSMEM (4*ATB)                // 73728

__global__ __launch_bounds__(256) void gemm_mma(const float* __restrict__ A,
                                                const float* __restrict__ stats,
                                                const float* __restrict__ lg,
                                                const float* __restrict__ lb,
                                                const float* __restrict__ W,
                                                const float* __restrict__ bias,
                                                float* __restrict__ C,
                                                int M, int N, int K) {
    extern __shared__ char smem[];
    unsigned short* sAhi = (unsigned short*)(smem);
    unsigned short* sAlo = (unsigned short*)(smem + ATB);
    unsigned short* sBhi = (unsigned short*)(smem + 2*ATB);
    unsigned short* sBlo = (unsigned short*)(smem + 3*ATB);

    int t = threadIdx.x, wid = t >> 5, lane = t & 31;
    int wm = wid >> 2, wn = wid & 3;            // 2 x 4 warp grid
    int bm = blockIdx.x * 128, bn = blockIdx.y * 128;

    // A loader mapping: row = t>>1, k-base = (t&1)*32
    int ar = t >> 1, akb = (t & 1) * 32;
    float m  = stats[2 * (bm + ar)];
    float iv = stats[2 * (bm + ar) + 1];
    const float* Ap = A + (size_t)(bm + ar) * K + akb;

    // fragment indices
    int fr = lane >> 2;        // 0..7
    int fc = lane & 3;         // 0..3

    float acc[4][4][4] = {};

    int NC = K / 64;
    for (int c = 0; c < NC; c++) {
        int k0g = c * 64;
        if (c) __syncthreads();     // previous compute done before overwrite

        // ---- A tile: fused LN + bf16 hi/lo split ----
        #pragma unroll
        for (int j = 0; j < 4; j++) {
            int kk = akb + j * 8;
            float4 a0 = *(const float4*)(Ap + k0g + j * 8);
            float4 a1 = *(const float4*)(Ap + k0g + j * 8 + 4);
            float4 g0 = *(const float4*)(lg + k0g + kk);
            float4 g1 = *(const float4*)(lg + k0g + kk + 4);
            float4 c0 = *(const float4*)(lb + k0g + kk);
            float4 c1 = *(const float4*)(lb + k0g + kk + 4);
            float v[8];
            v[0]=(a0.x-m)*iv*g0.x+c0.x; v[1]=(a0.y-m)*iv*g0.y+c0.y;
            v[2]=(a0.z-m)*iv*g0.z+c0.z; v[3]=(a0.w-m)*iv*g0.w+c0.w;
            v[4]=(a1.x-m)*iv*g1.x+c1.x; v[5]=(a1.y-m)*iv*g1.y+c1.y;
            v[6]=(a1.z-m)*iv*g1.z+c1.z; v[7]=(a1.w-m)*iv*g1.w+c1.w;
            uint4 hi, lo;
            unsigned short h[8], l[8];
            #pragma unroll
            for (int q = 0; q < 8; q++) {
                h[q] = f2bf(v[q]);
                l[q] = f2bf(v[q] - bf2f(h[q]));
            }
            hi.x = h[0] | (h[1] << 16); hi.y = h[2] | (h[3] << 16);
            hi.z = h[4] | (h[5] << 16); hi.w = h[6] | (h[7] << 16);
            lo.x = l[0] | (l[1] << 16); lo.y = l[2] | (l[3] << 16);
            lo.z = l[4] | (l[5] << 16); lo.w = l[6] | (l[7] << 16);
            *(uint4*)&sAhi[ar * AP + kk] = hi;
            *(uint4*)&sAlo[ar * AP + kk] = lo;
        }
        // ---- B tile: transpose W[k][n] -> [n][k], hi/lo ----
        #pragma unroll
        for (int i = 0; i < 4; i++) {
            int task = i * 256 + t;
            int n = task >> 3, g = task & 7;
            const float* wp = W + (size_t)(k0g + g * 8) * N + bn + n;
            float v[8];
            #pragma unroll
            for (int kk = 0; kk < 8; kk++) v[kk] = wp[(size_t)kk * N];
            uint4 hi, lo;
            unsigned short h[8], l[8];
            #pragma unroll
            for (int q = 0; q < 8; q++) {
                h[q] = f2bf(v[q]);
                l[q] = f2bf(v[q] - bf2f(h[q]));
            }
            hi.x = h[0] | (h[1] << 16); hi.y = h[2] | (h[3] << 16);
            hi.z = h[4] | (h[5] << 16); hi.w = h[6] | (h[7] << 16);
            lo.x = l[0] | (l[1] << 16); lo.y = l[2] | (l[3] << 16);
            lo.z = l[4] | (l[5] << 16); lo.w = l[6] | (l[7] << 16);
            *(uint4*)&sBhi[n * AP + g * 8] = hi;
            *(uint4*)&sBlo[n * AP + g * 8] = lo;
        }
        __syncthreads();

        // ---- compute: 4 k-steps of m16n8k16 ----
        const uint32_t* Ah = (const uint32_t*)sAhi;
        const uint32_t* Al = (const uint32_t*)sAlo;
        const uint32_t* Bh = (const uint32_t*)sBhi;
        const uint32_t* Bl = (const uint32_t*)sBlo;
        #pragma unroll
        for (int ks = 0; ks < 4; ks++) {
            int kw = ks * 8;     // k0/2 in 32-bit words (16 bf16 = 8 words)
            uint32_t ahi[4][4], alo[4][4], bhi[4][2], blo[4][2];
            #pragma unroll
            for (int mi = 0; mi < 4; mi++) {
                int r0 = (wm * 64 + mi * 16 + fr) * (AP/2) + kw + fc;
                int r1 = r0 + 8 * (AP/2);
                ahi[mi][0] = Ah[r0];     ahi[mi][1] = Ah[r1];
                ahi[mi][2] = Ah[r0 + 4]; ahi[mi][3] = Ah[r1 + 4];
                alo[mi][0] = Al[r0];     alo[mi][1] = Al[r1];
                alo[mi][2] = Al[r0 + 4]; alo[mi][3] = Al[r1 + 4];
            }
            #pragma unroll
            for (int ni = 0; ni < 4; ni++) {
                int n0 = (wn * 32 + ni * 8 + fr) * (AP/2) + kw + fc;
                bhi[ni][0] = Bh[n0]; bhi[ni][1] = Bh[n0 + 4];
                blo[ni][0] = Bl[n0]; blo[ni][1] = Bl[n0 + 4];
            }
            #pragma unroll
            for (int mi = 0; mi < 4; mi++)
                #pragma unroll
                for (int ni = 0; ni < 4; ni++) {
                    mma_bf16(acc[mi][ni], ahi[mi], bhi[ni]);
                    mma_bf16(acc[mi][ni], alo[mi], bhi[ni]);
                    mma_bf16(acc[mi][ni], ahi[mi], blo[ni]);
                }
        }
    }

    // ---- epilogue: bias + leaky, direct to global ----
    #pragma unroll
    for (int mi = 0; mi < 4; mi++) {
        int row0 = bm + wm * 64 + mi * 16 + fr;
        #pragma unroll
        for (int ni = 0; ni < 4; ni++) {
            int col = bn + wn * 32 + ni * 8 + fc * 2;
            float2 bb = *(const float2*)(bias + col);
            float2 o0, o1;
            o0.x = leaky(acc[mi][ni][0] + bb.x);
            o0.y = leaky(acc[mi][ni][1] + bb.y);
            o1.x = leaky(acc[mi][ni][2] + bb.x);
            o1.y = leaky(acc[mi][ni][3] + bb.y);
            *(float2*)(C + (size_t)row0 * N + col)       = o0;
            *(float2*)(C + (size_t)(row0 + 8) * N + col) = o1;
        }
    }
}

// ---------------- fused attention scorer ----------------
__global__ __launch_bounds__(256) void attn_kernel(const float* __restrict__ x,
                                                   const float* __restrict__ w1,
                                                   const float* __restrict__ b1,
                                                   const float* __restrict__ lng,
                                                   const float* __restrict__ lnb,
                                                   const float* __restrict__ w2,
                                                   const float* __restrict__ b2,
                                                   const int*  __restrict__ mask,
                                                   float* __restrict__ att) {
    __shared__ float xs[32][256];
    __shared__ float t1[32][64];
    __shared__ float mrow[32], irow[32];
    int t  = threadIdx.x;
    int r0 = blockIdx.x * 32;

    const float4* xsrc = (const float4*)(x + (size_t)r0 * 256);
    float4* xdst = (float4*)&xs[0][0];
    #pragma unroll
    for (int i = 0; i < 8; i++) xdst[t + i * 256] = xsrc[t + i * 256];
    __syncthreads();

    #pragma unroll
    for (int o = 0; o < 8; o++) {
        int idx = o * 256 + t;
        int r = idx >> 6, c = idx & 63;
        float acc = b1[c];
        #pragma unroll 4
        for (int k = 0; k < 256; k++) acc += xs[r][k] * w1[k * 64 + c];
        t1[r][c] = leaky(acc);
    }
    __syncthreads();

    if (t < 32) {
        float s = 0.f, q = 0.f;
        #pragma unroll
        for (int k = 0; k < 64; k++) { float v = t1[t][k]; s += v; q += v * v; }
        float m = s * (1.f / 64.f), var = q * (1.f / 64.f) - m * m;
        mrow[t] = m; irow[t] = rsqrtf(var + 1e-6f);
    }
    __syncthreads();
    #pragma unroll
    for (int o = 0; o < 8; o++) {
        int idx = o * 256 + t;
        int r = idx >> 6, c = idx & 63;
        t1[r][c] = (t1[r][c] - mrow[r]) * irow[r] * lng[c] + lnb[c];
    }
    __syncthreads();

    int r = t >> 3, hd = t & 7;
    float acc = b2[hd];
    #pragma unroll
    for (int k = 0; k < 64; k++) acc += t1[r][k] * w2[k * 8 + hd];
    int gr = r0 + r;
    int b = gr >> 10, l = gr & 1023;
    if (mask[b * 1024 + l] == 0) acc = -1e9f;
    att[((size_t)b * NH_ + hd) * L_ + l] = acc;
}

// ---------------- softmax ----------------
__global__ __launch_bounds__(256) void softmax_kernel(float* __restrict__ att) {
    __shared__ float s[256];
    float* row = att + (size_t)blockIdx.x * L_;
    int t = threadIdx.x;
    float v[4]; float mx = -1e30f;
    #pragma unroll
    for (int i = 0; i < 4; i++) { v[i] = row[t + i * 256]; mx = fmaxf(mx, v[i]); }
    s[t] = mx; __syncthreads();
    for (int st = 128; st > 0; st >>= 1) { if (t < st) s[t] = fmaxf(s[t], s[t + st]); __syncthreads(); }
    mx = s[0]; __syncthreads();
    float sum = 0.f;
    #pragma unroll
    for (int i = 0; i < 4; i++) { v[i] = expf(v[i] - mx); sum += v[i]; }
    s[t] = sum; __syncthreads();
    for (int st = 128; st > 0; st >>= 1) { if (t < st) s[t] += s[t + st]; __syncthreads(); }
    float inv = 1.f / s[0];
    #pragma unroll
    for (int i = 0; i < 4; i++) row[t + i * 256] = v[i] * inv;
}

// ---------------- pooling ----------------
__global__ __launch_bounds__(256) void pool_partial(const float* __restrict__ x,
                                                    const float* __restrict__ att,
                                                    float* __restrict__ part) {
    int chunk = blockIdx.x, b = blockIdx.y;
    int t = threadIdx.x;
    __shared__ float as[8][64];
    int l0 = chunk * 64;
    for (int i = t; i < 512; i += 256) {
        int hd = i >> 6, l = i & 63;
        as[hd][l] = att[((size_t)b * NH_ + hd) * L_ + l0 + l];
    }
    __syncthreads();
    float acc[8] = {};
    for (int l = 0; l < 64; l++) {
        float xv = x[((size_t)b * L_ + l0 + l) * H_ + t];
        #pragma unroll
        for (int hd = 0; hd < 8; hd++) acc[hd] += as[hd][l] * xv;
    }
    #pragma unroll
    for (int hd = 0; hd < 8; hd++)
        part[(((size_t)b * 16 + chunk) * NH_ + hd) * H_ + t] = acc[hd];
}

__global__ __launch_bounds__(256) void pool_reduce(const float* __restrict__ part,
                                                   float* __restrict__ h) {
    int hd = blockIdx.x, b = blockIdx.y, t = threadIdx.x;
    float s = 0.f;
    #pragma unroll
    for (int c = 0; c < 16; c++)
        s += part[(((size_t)b * 16 + c) * NH_ + hd) * H_ + t];
    h[(size_t)b * OH_ + hd * H_ + t] = s;
}

// ---------------- M=8 output GEMM: split-K ----------------
__global__ __launch_bounds__(256) void out_partial(const float* __restrict__ h,
                                                   const float* __restrict__ w,
                                                   float* __restrict__ part, int N) {
    __shared__ float hs[8][128];
    int t = threadIdx.x;
    int j = blockIdx.x * 256 + t;
    int k0 = blockIdx.y * 128;
    for (int i = t; i < 1024; i += 256)
        hs[i >> 7][i & 127] = h[(size_t)(i >> 7) * OH_ + k0 + (i & 127)];
    __syncthreads();
    if (j >= N) return;
    float acc[8] = {};
    const float* wp = w + (size_t)k0 * N + j;
    #pragma unroll 8
    for (int kk = 0; kk < 128; kk++) {
        float wv = wp[(size_t)kk * N];
        #pragma unroll
        for (int b = 0; b < 8; b++) acc[b] += hs[b][kk] * wv;
    }
    float* pp = part + (size_t)(blockIdx.y * 8) * N + j;
    #pragma unroll
    for (int b = 0; b < 8; b++) pp[(size_t)b * N] = acc[b];
}

template<int MODE>
__global__ __launch_bounds__(256) void out_reduce(const float* __restrict__ part,
                                                  const float* __restrict__ bias,
                                                  float* __restrict__ o, int N) {
    int j = blockIdx.x * 256 + threadIdx.x;
    if (j >= N) return;
    float s[8] = {};
    #pragma unroll
    for (int ks = 0; ks < 16; ks++)
        #pragma unroll
        for (int b = 0; b < 8; b++)
            s[b] += part[(size_t)(ks * 8 + b) * N + j];
    float bb = bias[j];
    #pragma unroll
    for (int b = 0; b < 8; b++) {
        float v = s[b] + bb;
        o[(size_t)b * N + j] = MODE ? (1.f / (1.f + expf(-v))) : leaky(v);
    }
}

// ---------------- GO max-propagation ----------------
__global__ __launch_bounds__(256) void maxprop_kernel(const float* __restrict__ p,
                                                      const float* __restrict__ CM,
                                                      float* __restrict__ out) {
    int i = blockIdx.x, t = threadIdx.x;
    __shared__ float red[256][9];
    float acc[8] = {};
    const float* row = CM + (size_t)i * LBL_;
    for (int j = t; j < LBL_; j += 256) {
        float c = row[j];
        if (c != 0.f) {
            #pragma unroll
            for (int b = 0; b < 8; b++)
                acc[b] = fmaxf(acc[b], p[(size_t)b * LBL_ + j] * c);
        }
    }
    #pragma unroll
    for (int b = 0; b < 8; b++) red[t][b] = acc[b];
    __syncthreads();
    for (int s = 128; s > 0; s >>= 1) {
        if (t < s) {
            #pragma unroll
            for (int b = 0; b < 8; b++) red[t][b] = fmaxf(red[t][b], red[t + s][b]);
        }
        __syncthreads();
    }
    if (t < 8) out[(size_t)t * LBL_ + i] = red[0][t];
}

// ---------------- launch ----------------
extern "C" void kernel_launch(void* const* d_in, const int* in_sizes, int n_in,
                              void* d_out, int out_size) {
    const float* h_V   = (const float*)d_in[0];
    const int*   mask  = (const int*)  d_in[1];
    const float* ln0_g = (const float*)d_in[2];
    const float* ln0_b = (const float*)d_in[3];
    const float* w_in  = (const float*)d_in[4];
    const float* b_in  = (const float*)d_in[5];
    const float* ln1_g = (const float*)d_in[6];
    const float* ln1_b = (const float*)d_in[7];
    const float* w_h   = (const float*)d_in[8];
    const float* b_h   = (const float*)d_in[9];
    const float* ln2_g = (const float*)d_in[10];
    const float* ln2_b = (const float*)d_in[11];
    const float* a_w1  = (const float*)d_in[12];
    const float* a_b1  = (const float*)d_in[13];
    const float* a_lng = (const float*)d_in[14];
    const float* a_lnb = (const float*)d_in[15];
    const float* a_w2  = (const float*)d_in[16];
    const float* a_b2  = (const float*)d_in[17];
    const float* o_w1  = (const float*)d_in[18];
    const float* o_b1  = (const float*)d_in[19];
    const float* o_lng = (const float*)d_in[20];
    const float* o_lnb = (const float*)d_in[21];
    const float* o_w2  = (const float*)d_in[22];
    const float* o_b2  = (const float*)d_in[23];
    const float* CM    = (const float*)d_in[24];
    float* out = (float*)d_out;

    float *x1, *x2, *stats, *att, *part, *hb, *h1, *p, *op1, *op2;
    cudaGetSymbolAddress((void**)&x1,    g_x1);
    cudaGetSymbolAddress((void**)&x2,    g_x2);
    cudaGetSymbolAddress((void**)&stats, g_stats);
    cudaGetSymbolAddress((void**)&att,   g_att);
    cudaGetSymbolAddress((void**)&part,  g_part);
    cudaGetSymbolAddress((void**)&hb,    g_h);
    cudaGetSymbolAddress((void**)&h1,    g_h1);
    cudaGetSymbolAddress((void**)&p,     g_p);
    cudaGetSymbolAddress((void**)&op1,   g_op1);
    cudaGetSymbolAddress((void**)&op2,   g_op2);

    cudaFuncSetAttribute(gemm_mma, cudaFuncAttributeMaxDynamicSharedMemorySize, GSMEM);

    // input block: LN0 fused into GEMM1 (HMMA bf16 3-term)
    rowstat_kernel<1024><<<ROWS_, 256>>>(h_V, stats);
    gemm_mma<<<dim3(ROWS_/128, H_/128), 256, GSMEM>>>(h_V, stats, ln0_g, ln0_b,
                                                      w_in, b_in, x1, ROWS_, H_, F_);
    // hidden block: LN1 fused into GEMM2
    rowstat_kernel<256><<<ROWS_, 256>>>(x1, stats);
    gemm_mma<<<dim3(ROWS_/128, H_/128), 256, GSMEM>>>(x1, stats, ln1_g, ln1_b,
                                                      w_h, b_h, x2, ROWS_, H_, H_);
    ln_kernel<256><<<ROWS_, 256>>>(x2, x2, ln2_g, ln2_b);

    // attention pooling
    attn_kernel<<<ROWS_/32, 256>>>(x2, a_w1, a_b1, a_lng, a_lnb, a_w2, a_b2, mask, att);
    softmax_kernel<<<B_*NH_, 256>>>(att);
    pool_partial<<<dim3(16, B_), 256>>>(x2, att, part);
    pool_reduce<<<dim3(NH_, B_), 256>>>(part, hb);

    // output block (split-K)
    out_partial<<<dim3(OH_/256, 16), 256>>>(hb, o_w1, op1, OH_);
    out_reduce<0><<<OH_/256, 256>>>(op1, o_b1, h1, OH_);
    ln_kernel<2048><<<B_, 256>>>(h1, h1, o_lng, o_lnb);
    out_partial<<<dim3((LBL_+255)/256, 16), 256>>>(h1, o_w2, op2, LBL_);
    out_reduce<1><<<(LBL_+255)/256, 256>>>(op2, o_b2, p, LBL_);

    // GO hierarchy max-product
    maxprop_kernel<<<LBL_, 256>>>(p, CM, out);
}

// round 9
// speedup vs baseline: 1.4451x; 1.4451x over previous
#include <cuda_runtime.h>
#include <cuda_bf16.h>
#include <math.h>
#include <stdint.h>

// ---------------- shapes ----------------
#define B_    8
#define L_    1024
#define F_    1024
#define H_    256
#define NH_   8
#define LBL_  4766
#define ROWS_ (B_*L_)      // 8192
#define OH_   (NH_*H_)     // 2048

// ---------------- scratch ----------------
__device__ float g_x1[ROWS_*H_];
__device__ float g_x2[ROWS_*H_];
__device__ float g_att[B_*NH_*L_];
__device__ float g_part[B_*16*NH_*H_];
__device__ float g_h[B_*OH_];
__device__ float g_h1[B_*OH_];
__device__ float g_p[B_*LBL_];
__device__ float g_op1[16*8*OH_];
__device__ float g_op2[16*8*LBL_];
// bf16 hi/lo planes (pre-converted operands)
__device__ __align__(16) unsigned short g_Ahi[ROWS_*F_];
__device__ __align__(16) unsigned short g_Alo[ROWS_*F_];
__device__ __align__(16) unsigned short g_Whi[H_*F_];
__device__ __align__(16) unsigned short g_Wlo[H_*F_];

// ---------------- helpers ----------------
__device__ __forceinline__ float leaky(float v) { return v >= 0.f ? v : 0.01f * v; }
__device__ __forceinline__ unsigned short f2bf(float f) {
    return __bfloat16_as_ushort(__float2bfloat16_rn(f));
}
__device__ __forceinline__ float bf2f(unsigned short u) {
    return __bfloat162float(__ushort_as_bfloat16(u));
}
__device__ __forceinline__ uint32_t smem_u32(const void* p) {
    uint32_t a;
    asm("{ .reg .u64 t; cvta.to.shared.u64 t, %1; cvt.u32.u64 %0, t; }" : "=r"(a) : "l"(p));
    return a;
}
__device__ __forceinline__ void cp16(uint32_t dst, const void* src) {
    asm volatile("cp.async.cg.shared.global [%0], [%1], 16;" :: "r"(dst), "l"(src));
}
#define CP_COMMIT() asm volatile("cp.async.commit_group;" ::: "memory")
#define CP_WAIT(n)  asm volatile("cp.async.wait_group %0;" :: "n"(n) : "memory")

__device__ __forceinline__ void mma_bf16(float* d, const uint32_t* a, const uint32_t* b) {
    asm volatile(
        "mma.sync.aligned.m16n8k16.row.col.f32.bf16.bf16.f32 "
        "{%0,%1,%2,%3}, {%4,%5,%6,%7}, {%8,%9}, {%0,%1,%2,%3};"
        : "+f"(d[0]), "+f"(d[1]), "+f"(d[2]), "+f"(d[3])
        : "r"(a[0]), "r"(a[1]), "r"(a[2]), "r"(a[3]), "r"(b[0]), "r"(b[1]));
}

__device__ __forceinline__ void block_reduce2(float& a, float& b, float* s) {
    int t = threadIdx.x;
    s[t] = a; s[256 + t] = b; __syncthreads();
    #pragma unroll
    for (int st = 128; st > 0; st >>= 1) {
        if (t < st) { s[t] += s[t + st]; s[256 + t] += s[256 + t + st]; }
        __syncthreads();
    }
    a = s[0]; b = s[256];
    __syncthreads();
}

// ---------------- convA: fused rowstat + LN + bf16 hi/lo split ----------------
template<int NF>
__global__ __launch_bounds__(256) void convA(const float* __restrict__ in,
                                             unsigned short* __restrict__ hi,
                                             unsigned short* __restrict__ lo,
                                             const float* __restrict__ g,
                                             const float* __restrict__ b) {
    constexpr int VPT = NF / 256;
    __shared__ float s[512];
    int t = threadIdx.x;
    size_t rb = (size_t)blockIdx.x * NF;
    const float* row = in + rb;
    int c0 = t * VPT;
    float v[VPT];
    float sum = 0.f, sq = 0.f;
    #pragma unroll
    for (int i = 0; i < VPT; i++) {
        v[i] = row[c0 + i];
        sum += v[i]; sq += v[i] * v[i];
    }
    block_reduce2(sum, sq, s);
    float m   = sum * (1.0f / NF);
    float var = sq  * (1.0f / NF) - m * m;
    float inv = rsqrtf(var + 1e-6f);
    #pragma unroll
    for (int i = 0; i < VPT; i++) {
        int c = c0 + i;
        float val = (v[i] - m) * inv * g[c] + b[c];
        unsigned short h = f2bf(val);
        hi[rb + c] = h;
        lo[rb + c] = f2bf(val - bf2f(h));
    }
}

// ---------------- convW: transpose W[K,N] -> [n][k] bf16 hi/lo ----------------
__global__ __launch_bounds__(256) void convW(const float* __restrict__ w,
                                             unsigned short* __restrict__ whi,
                                             unsigned short* __restrict__ wlo,
                                             int K, int N) {
    __shared__ float s[32][33];
    int t = threadIdx.x;
    int n0 = blockIdx.x * 32, k0 = blockIdx.y * 32;
    #pragma unroll
    for (int i = 0; i < 4; i++) {
        int idx = i * 256 + t;
        int kr = idx >> 5, nc = idx & 31;
        s[kr][nc] = w[(size_t)(k0 + kr) * N + n0 + nc];
    }
    __syncthreads();
    #pragma unroll
    for (int i = 0; i < 4; i++) {
        int idx = i * 256 + t;
        int nr = idx >> 5, kc = idx & 31;
        float v = s[kc][nr];
        unsigned short h = f2bf(v);
        size_t o = (size_t)(n0 + nr) * K + k0 + kc;
        whi[o] = h;
        wlo[o] = f2bf(v - bf2f(h));
    }
}

// ============ HMMA bf16 GEMM (pre-converted operands, cp.async pipeline) ======
// C = leaky( A @ W^T + bias ), A planes [M][K] bf16, W planes [N][K] bf16.
// 3-term hi/lo. Tile 128x128, BK=64, double-buffered. 8 warps (2x4), 64x32 each.
#define PITCH 72
#define PLANE (128*PITCH)            // bf16 elems per plane tile (18432 B)
#define BUFE  (4*PLANE)              // elems per buffer (4 planes)
#define GSMEM (2*BUFE*2)             // bytes: 2 buffers

__global__ __launch_bounds__(256) void gemm_bf(const unsigned short* __restrict__ Ahi,
                                               const unsigned short* __restrict__ Alo,
                                               const unsigned short* __restrict__ Bhi,
                                               const unsigned short* __restrict__ Blo,
                                               const float* __restrict__ bias,
                                               float* __restrict__ C,
                                               int M, int N, int K) {
    extern __shared__ unsigned short sm[];
    uint32_t sbase = smem_u32(sm);

    int t = threadIdx.x, wid = t >> 5, lane = t & 31;
    int wm = wid >> 2, wn = wid & 3;
    int bm = blockIdx.x * 128, bn = blockIdx.y * 128;
    int fr = lane >> 2, fc = lane & 3;

    // loader mapping: row = t>>1 (0..127), half = t&1 (32 bf16 = 64B = 4 cp16)
    int lr = t >> 1, lh = t & 1;
    const unsigned short* pA[2] = { Ahi + (size_t)(bm + lr) * K + lh * 32,
                                    Alo + (size_t)(bm + lr) * K + lh * 32 };
    const unsigned short* pB[2] = { Bhi + (size_t)(bn + lr) * K + lh * 32,
                                    Blo + (size_t)(bn + lr) * K + lh * 32 };
    uint32_t dbase = sbase + 2u * (uint32_t)(lr * PITCH + lh * 32);

    auto load_chunk = [&](int c, int buf) {
        uint32_t db = dbase + 2u * (uint32_t)(buf * BUFE);
        int ko = c * 64;
        #pragma unroll
        for (int pl = 0; pl < 2; pl++) {
            const char* sa = (const char*)(pA[pl] + ko);
            const char* sb = (const char*)(pB[pl] + ko);
            uint32_t da = db + 2u * (uint32_t)(pl * PLANE);
            uint32_t dbb = db + 2u * (uint32_t)((2 + pl) * PLANE);
            #pragma unroll
            for (int j = 0; j < 4; j++) {
                cp16(da  + j * 16, sa + j * 16);
                cp16(dbb + j * 16, sb + j * 16);
            }
        }
    };

    float acc[4][4][4] = {};

    int NC = K / 64;
    load_chunk(0, 0);
    CP_COMMIT();

    for (int c = 0; c < NC; c++) {
        int buf = c & 1;
        if (c + 1 < NC) {
            load_chunk(c + 1, buf ^ 1);
            CP_COMMIT();
            CP_WAIT(1);
        } else {
            CP_WAIT(0);
        }
        __syncthreads();

        const uint32_t* Ah = (const uint32_t*)(sm + buf * BUFE);
        const uint32_t* Al = (const uint32_t*)(sm + buf * BUFE + PLANE);
        const uint32_t* Bh = (const uint32_t*)(sm + buf * BUFE + 2 * PLANE);
        const uint32_t* Bl = (const uint32_t*)(sm + buf * BUFE + 3 * PLANE);
        #pragma unroll
        for (int ks = 0; ks < 4; ks++) {
            int kw = ks * 8;
            uint32_t ahi[4][4], alo[4][4], bhi[4][2], blo[4][2];
            #pragma unroll
            for (int mi = 0; mi < 4; mi++) {
                int r0 = (wm * 64 + mi * 16 + fr) * (PITCH/2) + kw + fc;
                int r1 = r0 + 8 * (PITCH/2);
                ahi[mi][0] = Ah[r0];     ahi[mi][1] = Ah[r1];
                ahi[mi][2] = Ah[r0 + 4]; ahi[mi][3] = Ah[r1 + 4];
                alo[mi][0] = Al[r0];     alo[mi][1] = Al[r1];
                alo[mi][2] = Al[r0 + 4]; alo[mi][3] = Al[r1 + 4];
            }
            #pragma unroll
            for (int ni = 0; ni < 4; ni++) {
                int n0 = (wn * 32 + ni * 8 + fr) * (PITCH/2) + kw + fc;
                bhi[ni][0] = Bh[n0]; bhi[ni][1] = Bh[n0 + 4];
                blo[ni][0] = Bl[n0]; blo[ni][1] = Bl[n0 + 4];
            }
            #pragma unroll
            for (int mi = 0; mi < 4; mi++)
                #pragma unroll
                for (int ni = 0; ni < 4; ni++) {
                    mma_bf16(acc[mi][ni], ahi[mi], bhi[ni]);
                    mma_bf16(acc[mi][ni], alo[mi], bhi[ni]);
                    mma_bf16(acc[mi][ni], ahi[mi], blo[ni]);
                }
        }
        __syncthreads();
    }

    // ---- epilogue: bias + leaky ----
    #pragma unroll
    for (int mi = 0; mi < 4; mi++) {
        int row0 = bm + wm * 64 + mi * 16 + fr;
        #pragma unroll
        for (int ni = 0; ni < 4; ni++) {
            int col = bn + wn * 32 + ni * 8 + fc * 2;
            float2 bb = *(const float2*)(bias + col);
            float2 o0, o1;
            o0.x = leaky(acc[mi][ni][0] + bb.x);
            o0.y = leaky(acc[mi][ni][1] + bb.y);
            o1.x = leaky(acc[mi][ni][2] + bb.x);
            o1.y = leaky(acc[mi][ni][3] + bb.y);
            *(float2*)(C + (size_t)row0 * N + col)       = o0;
            *(float2*)(C + (size_t)(row0 + 8) * N + col) = o1;
        }
    }
}

// ---------------- full LayerNorm ----------------
template<int NF>
__global__ __launch_bounds__(256) void ln_kernel(const float* __restrict__ in,
                                                 float* __restrict__ out,
                                                 const float* __restrict__ g,
                                                 const float* __restrict__ b) {
    constexpr int VPT = NF / 256;
    __shared__ float s[512];
    const float* row = in + (size_t)blockIdx.x * NF;
    float v[VPT];
    float sum = 0.f, sq = 0.f;
    #pragma unroll
    for (int i = 0; i < VPT; i++) {
        v[i] = row[threadIdx.x + i * 256];
        sum += v[i]; sq += v[i] * v[i];
    }
    block_reduce2(sum, sq, s);
    float m   = sum * (1.0f / NF);
    float var = sq  * (1.0f / NF) - m * m;
    float inv = rsqrtf(var + 1e-6f);
    float* orow = out + (size_t)blockIdx.x * NF;
    #pragma unroll
    for (int i = 0; i < VPT; i++) {
        int c = threadIdx.x + i * 256;
        orow[c] = (v[i] - m) * inv * g[c] + b[c];
    }
}

// ---------------- fused attention scorer ----------------
__global__ __launch_bounds__(256) void attn_kernel(const float* __restrict__ x,
                                                   const float* __restrict__ w1,
                                                   const float* __restrict__ b1,
                                                   const float* __restrict__ lng,
                                                   const float* __restrict__ lnb,
                                                   const float* __restrict__ w2,
                                                   const float* __restrict__ b2,
                                                   const int*  __restrict__ mask,
                                                   float* __restrict__ att) {
    __shared__ float xs[32][256];
    __shared__ float t1[32][64];
    __shared__ float mrow[32], irow[32];
    int t  = threadIdx.x;
    int r0 = blockIdx.x * 32;

    const float4* xsrc = (const float4*)(x + (size_t)r0 * 256);
    float4* xdst = (float4*)&xs[0][0];
    #pragma unroll
    for (int i = 0; i < 8; i++) xdst[t + i * 256] = xsrc[t + i * 256];
    __syncthreads();

    #pragma unroll
    for (int o = 0; o < 8; o++) {
        int idx = o * 256 + t;
        int r = idx >> 6, c = idx & 63;
        float acc = b1[c];
        #pragma unroll 4
        for (int k = 0; k < 256; k++) acc += xs[r][k] * w1[k * 64 + c];
        t1[r][c] = leaky(acc);
    }
    __syncthreads();

    if (t < 32) {
        float s = 0.f, q = 0.f;
        #pragma unroll
        for (int k = 0; k < 64; k++) { float v = t1[t][k]; s += v; q += v * v; }
        float m = s * (1.f / 64.f), var = q * (1.f / 64.f) - m * m;
        mrow[t] = m; irow[t] = rsqrtf(var + 1e-6f);
    }
    __syncthreads();
    #pragma unroll
    for (int o = 0; o < 8; o++) {
        int idx = o * 256 + t;
        int r = idx >> 6, c = idx & 63;
        t1[r][c] = (t1[r][c] - mrow[r]) * irow[r] * lng[c] + lnb[c];
    }
    __syncthreads();

    int r = t >> 3, hd = t & 7;
    float acc = b2[hd];
    #pragma unroll
    for (int k = 0; k < 64; k++) acc += t1[r][k] * w2[k * 8 + hd];
    int gr = r0 + r;
    int b = gr >> 10, l = gr & 1023;
    if (mask[b * 1024 + l] == 0) acc = -1e9f;
    att[((size_t)b * NH_ + hd) * L_ + l] = acc;
}

// ---------------- softmax ----------------
__global__ __launch_bounds__(256) void softmax_kernel(float* __restrict__ att) {
    __shared__ float s[256];
    float* row = att + (size_t)blockIdx.x * L_;
    int t = threadIdx.x;
    float v[4]; float mx = -1e30f;
    #pragma unroll
    for (int i = 0; i < 4; i++) { v[i] = row[t + i * 256]; mx = fmaxf(mx, v[i]); }
    s[t] = mx; __syncthreads();
    for (int st = 128; st > 0; st >>= 1) { if (t < st) s[t] = fmaxf(s[t], s[t + st]); __syncthreads(); }
    mx = s[0]; __syncthreads();
    float sum = 0.f;
    #pragma unroll
    for (int i = 0; i < 4; i++) { v[i] = expf(v[i] - mx); sum += v[i]; }
    s[t] = sum; __syncthreads();
    for (int st = 128; st > 0; st >>= 1) { if (t < st) s[t] += s[t + st]; __syncthreads(); }
    float inv = 1.f / s[0];
    #pragma unroll
    for (int i = 0; i < 4; i++) row[t + i * 256] = v[i] * inv;
}

// ---------------- pooling ----------------
__global__ __launch_bounds__(256) void pool_partial(const float* __restrict__ x,
                                                    const float* __restrict__ att,
                                                    float* __restrict__ part) {
    int chunk = blockIdx.x, b = blockIdx.y;
    int t = threadIdx.x;
    __shared__ float as[8][64];
    int l0 = chunk * 64;
    for (int i = t; i < 512; i += 256) {
        int hd = i >> 6, l = i & 63;
        as[hd][l] = att[((size_t)b * NH_ + hd) * L_ + l0 + l];
    }
    __syncthreads();
    float acc[8] = {};
    for (int l = 0; l < 64; l++) {
        float xv = x[((size_t)b * L_ + l0 + l) * H_ + t];
        #pragma unroll
        for (int hd = 0; hd < 8; hd++) acc[hd] += as[hd][l] * xv;
    }
    #pragma unroll
    for (int hd = 0; hd < 8; hd++)
        part[(((size_t)b * 16 + chunk) * NH_ + hd) * H_ + t] = acc[hd];
}

__global__ __launch_bounds__(256) void pool_reduce(const float* __restrict__ part,
                                                   float* __restrict__ h) {
    int hd = blockIdx.x, b = blockIdx.y, t = threadIdx.x;
    float s = 0.f;
    #pragma unroll
    for (int c = 0; c < 16; c++)
        s += part[(((size_t)b * 16 + c) * NH_ + hd) * H_ + t];
    h[(size_t)b * OH_ + hd * H_ + t] = s;
}

// ---------------- M=8 output GEMM: split-K ----------------
__global__ __launch_bounds__(256) void out_partial(const float* __restrict__ h,
                                                   const float* __restrict__ w,
                                                   float* __restrict__ part, int N) {
    __shared__ float hs[8][128];
    int t = threadIdx.x;
    int j = blockIdx.x * 256 + t;
    int k0 = blockIdx.y * 128;
    for (int i = t; i < 1024; i += 256)
        hs[i >> 7][i & 127] = h[(size_t)(i >> 7) * OH_ + k0 + (i & 127)];
    __syncthreads();
    if (j >= N) return;
    float acc[8] = {};
    const float* wp = w + (size_t)k0 * N + j;
    #pragma unroll 8
    for (int kk = 0; kk < 128; kk++) {
        float wv = wp[(size_t)kk * N];
        #pragma unroll
        for (int b = 0; b < 8; b++) acc[b] += hs[b][kk] * wv;
    }
    float* pp = part + (size_t)(blockIdx.y * 8) * N + j;
    #pragma unroll
    for (int b = 0; b < 8; b++) pp[(size_t)b * N] = acc[b];
}

template<int MODE>
__global__ __launch_bounds__(256) void out_reduce(const float* __restrict__ part,
                                                  const float* __restrict__ bias,
                                                  float* __restrict__ o, int N) {
    int j = blockIdx.x * 256 + threadIdx.x;
    if (j >= N) return;
    float s[8] = {};
    #pragma unroll
    for (int ks = 0; ks < 16; ks++)
        #pragma unroll
        for (int b = 0; b < 8; b++)
            s[b] += part[(size_t)(ks * 8 + b) * N + j];
    float bb = bias[j];
    #pragma unroll
    for (int b = 0; b < 8; b++) {
        float v = s[b] + bb;
        o[(size_t)b * N + j] = MODE ? (1.f / (1.f + expf(-v))) : leaky(v);
    }
}

// ---------------- GO max-propagation ----------------
__global__ __launch_bounds__(256) void maxprop_kernel(const float* __restrict__ p,
                                                      const float* __restrict__ CM,
                                                      float* __restrict__ out) {
    int i = blockIdx.x, t = threadIdx.x;
    __shared__ float red[256][9];
    float acc[8] = {};
    const float* row = CM + (size_t)i * LBL_;
    for (int j = t; j < LBL_; j += 256) {
        float c = row[j];
        if (c != 0.f) {
            #pragma unroll
            for (int b = 0; b < 8; b++)
                acc[b] = fmaxf(acc[b], p[(size_t)b * LBL_ + j] * c);
        }
    }
    #pragma unroll
    for (int b = 0; b < 8; b++) red[t][b] = acc[b];
    __syncthreads();
    for (int s = 128; s > 0; s >>= 1) {
        if (t < s) {
            #pragma unroll
            for (int b = 0; b < 8; b++) red[t][b] = fmaxf(red[t][b], red[t + s][b]);
        }
        __syncthreads();
    }
    if (t < 8) out[(size_t)t * LBL_ + i] = red[0][t];
}

// ---------------- launch ----------------
extern "C" void kernel_launch(void* const* d_in, const int* in_sizes, int n_in,
                              void* d_out, int out_size) {
    const float* h_V   = (const float*)d_in[0];
    const int*   mask  = (const int*)  d_in[1];
    const float* ln0_g = (const float*)d_in[2];
    const float* ln0_b = (const float*)d_in[3];
    const float* w_in  = (const float*)d_in[4];
    const float* b_in  = (const float*)d_in[5];
    const float* ln1_g = (const float*)d_in[6];
    const float* ln1_b = (const float*)d_in[7];
    const float* w_h   = (const float*)d_in[8];
    const float* b_h   = (const float*)d_in[9];
    const float* ln2_g = (const float*)d_in[10];
    const float* ln2_b = (const float*)d_in[11];
    const float* a_w1  = (const float*)d_in[12];
    const float* a_b1  = (const float*)d_in[13];
    const float* a_lng = (const float*)d_in[14];
    const float* a_lnb = (const float*)d_in[15];
    const float* a_w2  = (const float*)d_in[16];
    const float* a_b2  = (const float*)d_in[17];
    const float* o_w1  = (const float*)d_in[18];
    const float* o_b1  = (const float*)d_in[19];
    const float* o_lng = (const float*)d_in[20];
    const float* o_lnb = (const float*)d_in[21];
    const float* o_w2  = (const float*)d_in[22];
    const float* o_b2  = (const float*)d_in[23];
    const float* CM    = (const float*)d_in[24];
    float* out = (float*)d_out;

    float *x1, *x2, *att, *part, *hb, *h1, *p, *op1, *op2;
    unsigned short *Ahi, *Alo, *Whi, *Wlo;
    cudaGetSymbolAddress((void**)&x1,    g_x1);
    cudaGetSymbolAddress((void**)&x2,    g_x2);
    cudaGetSymbolAddress((void**)&att,   g_att);
    cudaGetSymbolAddress((void**)&part,  g_part);
    cudaGetSymbolAddress((void**)&hb,    g_h);
    cudaGetSymbolAddress((void**)&h1,    g_h1);
    cudaGetSymbolAddress((void**)&p,     g_p);
    cudaGetSymbolAddress((void**)&op1,   g_op1);
    cudaGetSymbolAddress((void**)&op2,   g_op2);
    cudaGetSymbolAddress((void**)&Ahi,   g_Ahi);
    cudaGetSymbolAddress((void**)&Alo,   g_Alo);
    cudaGetSymbolAddress((void**)&Whi,   g_Whi);
    cudaGetSymbolAddress((void**)&Wlo,   g_Wlo);

    cudaFuncSetAttribute(gemm_bf, cudaFuncAttributeMaxDynamicSharedMemorySize, GSMEM);

    // input block: LN0 + split fused into convA; GEMM1 on tensor cores
    convA<1024><<<ROWS_, 256>>>(h_V, Ahi, Alo, ln0_g, ln0_b);
    convW<<<dim3(H_/32, F_/32), 256>>>(w_in, Whi, Wlo, F_, H_);
    gemm_bf<<<dim3(ROWS_/128, H_/128), 256, GSMEM>>>(Ahi, Alo, Whi, Wlo, b_in, x1,
                                                     ROWS_, H_, F_);
    // hidden block
    convA<256><<<ROWS_, 256>>>(x1, Ahi, Alo, ln1_g, ln1_b);
    convW<<<dim3(H_/32, H_/32), 256>>>(w_h, Whi, Wlo, H_, H_);
    gemm_bf<<<dim3(ROWS_/128, H_/128), 256, GSMEM>>>(Ahi, Alo, Whi, Wlo, b_h, x2,
                                                     ROWS_, H_, H_);
    ln_kernel<256><<<ROWS_, 256>>>(x2, x2, ln2_g, ln2_b);

    // attention pooling
    attn_kernel<<<ROWS_/32, 256>>>(x2, a_w1, a_b1, a_lng, a_lnb, a_w2, a_b2, mask, att);
    softmax_kernel<<<B_*NH_, 256>>>(att);
    pool_partial<<<dim3(16, B_), 256>>>(x2, att, part);
    pool_reduce<<<dim3(NH_, B_), 256>>>(part, hb);

    // output block (split-K)
    out_partial<<<dim3(OH_/256, 16), 256>>>(hb, o_w1, op1, OH_);
    out_reduce<0><<<OH_/256, 256>>>(op1, o_b1, h1, OH_);
    ln_kernel<2048><<<B_, 256>>>(h1, h1, o_lng, o_lnb);
    out_partial<<<dim3((LBL_+255)/256, 16), 256>>>(h1, o_w2, op2, LBL_);
    out_reduce<1><<<(LBL_+255)/256, 256>>>(op2, o_b2, p, LBL_);

    // GO hierarchy max-product
    maxprop_kernel<<<LBL_, 256>>>(p, CM, out);
}

// round 10
// speedup vs baseline: 1.8053x; 1.2493x over previous
#include <cuda_runtime.h>
#include <cuda_bf16.h>
#include <math.h>
#include <stdint.h>

// ---------------- shapes ----------------
#define B_    8
#define L_    1024
#define F_    1024
#define H_    256
#define NH_   8
#define LBL_  4766
#define ROWS_ (B_*L_)      // 8192
#define OH_   (NH_*H_)     // 2048

// ---------------- scratch ----------------
__device__ float g_x1[ROWS_*H_];
__device__ float g_x2[ROWS_*H_];
__device__ float g_att[B_*NH_*L_];
__device__ float g_part[B_*16*NH_*H_];
__device__ float g_h[B_*OH_];
__device__ float g_h1[B_*OH_];
__device__ float g_p[B_*LBL_];
__device__ float g_op1[16*8*OH_];
__device__ float g_op2[16*8*LBL_];
__device__ __align__(16) unsigned short g_Ahi[ROWS_*F_];
__device__ __align__(16) unsigned short g_Alo[ROWS_*F_];
__device__ __align__(16) unsigned short g_Whi[H_*F_];
__device__ __align__(16) unsigned short g_Wlo[H_*F_];

// ---------------- helpers ----------------
__device__ __forceinline__ float leaky(float v) { return v >= 0.f ? v : 0.01f * v; }
__device__ __forceinline__ unsigned short f2bf(float f) {
    return __bfloat16_as_ushort(__float2bfloat16_rn(f));
}
__device__ __forceinline__ float bf2f(unsigned short u) {
    return __bfloat162float(__ushort_as_bfloat16(u));
}
__device__ __forceinline__ uint32_t smem_u32(const void* p) {
    uint32_t a;
    asm("{ .reg .u64 t; cvta.to.shared.u64 t, %1; cvt.u32.u64 %0, t; }" : "=r"(a) : "l"(p));
    return a;
}
__device__ __forceinline__ void cp16(uint32_t dst, const void* src) {
    asm volatile("cp.async.cg.shared.global [%0], [%1], 16;" :: "r"(dst), "l"(src));
}
#define CP_COMMIT() asm volatile("cp.async.commit_group;" ::: "memory")
#define CP_WAIT(n)  asm volatile("cp.async.wait_group %0;" :: "n"(n) : "memory")

__device__ __forceinline__ void mma_bf16(float* d, const uint32_t* a, const uint32_t* b) {
    asm volatile(
        "mma.sync.aligned.m16n8k16.row.col.f32.bf16.bf16.f32 "
        "{%0,%1,%2,%3}, {%4,%5,%6,%7}, {%8,%9}, {%0,%1,%2,%3};"
        : "+f"(d[0]), "+f"(d[1]), "+f"(d[2]), "+f"(d[3])
        : "r"(a[0]), "r"(a[1]), "r"(a[2]), "r"(a[3]), "r"(b[0]), "r"(b[1]));
}

__device__ __forceinline__ void pack8(const float* v, uint4& hi, uint4& lo) {
    unsigned short h[8], l[8];
    #pragma unroll
    for (int q = 0; q < 8; q++) {
        h[q] = f2bf(v[q]);
        l[q] = f2bf(v[q] - bf2f(h[q]));
    }
    hi.x = h[0] | (h[1] << 16); hi.y = h[2] | (h[3] << 16);
    hi.z = h[4] | (h[5] << 16); hi.w = h[6] | (h[7] << 16);
    lo.x = l[0] | (l[1] << 16); lo.y = l[2] | (l[3] << 16);
    lo.z = l[4] | (l[5] << 16); lo.w = l[6] | (l[7] << 16);
}

// ---------------- convA 256: warp-per-row (8 rows / CTA) ----------------
__global__ __launch_bounds__(256) void convA256(const float* __restrict__ in,
                                                unsigned short* __restrict__ hi,
                                                unsigned short* __restrict__ lo,
                                                const float* __restrict__ g,
                                                const float* __restrict__ b) {
    int wid = threadIdx.x >> 5, lane = threadIdx.x & 31;
    size_t row = (size_t)blockIdx.x * 8 + wid;
    const float4* rp = (const float4*)(in + row * 256);
    float4 v0 = rp[lane * 2], v1 = rp[lane * 2 + 1];
    float sum = v0.x+v0.y+v0.z+v0.w + v1.x+v1.y+v1.z+v1.w;
    float sq  = v0.x*v0.x+v0.y*v0.y+v0.z*v0.z+v0.w*v0.w
              + v1.x*v1.x+v1.y*v1.y+v1.z*v1.z+v1.w*v1.w;
    #pragma unroll
    for (int o = 16; o > 0; o >>= 1) {
        sum += __shfl_xor_sync(0xffffffffu, sum, o);
        sq  += __shfl_xor_sync(0xffffffffu, sq,  o);
    }
    float m   = sum * (1.f/256.f);
    float inv = rsqrtf(sq * (1.f/256.f) - m * m + 1e-6f);
    int c0 = lane * 8;
    float4 g0 = *(const float4*)(g + c0), g1 = *(const float4*)(g + c0 + 4);
    float4 b0 = *(const float4*)(b + c0), b1 = *(const float4*)(b + c0 + 4);
    float v[8];
    v[0]=(v0.x-m)*inv*g0.x+b0.x; v[1]=(v0.y-m)*inv*g0.y+b0.y;
    v[2]=(v0.z-m)*inv*g0.z+b0.z; v[3]=(v0.w-m)*inv*g0.w+b0.w;
    v[4]=(v1.x-m)*inv*g1.x+b1.x; v[5]=(v1.y-m)*inv*g1.y+b1.y;
    v[6]=(v1.z-m)*inv*g1.z+b1.z; v[7]=(v1.w-m)*inv*g1.w+b1.w;
    uint4 ph, pl;
    pack8(v, ph, pl);
    ((uint4*)(hi + row * 256))[lane] = ph;
    ((uint4*)(lo + row * 256))[lane] = pl;
}

// ---------------- convA 1024: block-per-row, float4, 2-level reduce ----------
__global__ __launch_bounds__(256) void convA1024(const float* __restrict__ in,
                                                 unsigned short* __restrict__ hi,
                                                 unsigned short* __restrict__ lo,
                                                 const float* __restrict__ g,
                                                 const float* __restrict__ b) {
    __shared__ float ws[16];
    int t = threadIdx.x, wid = t >> 5, lane = t & 31;
    size_t rb = (size_t)blockIdx.x * 1024;
    int c0 = t * 4;
    float4 v4 = *(const float4*)(in + rb + c0);
    float sum = v4.x + v4.y + v4.z + v4.w;
    float sq  = v4.x*v4.x + v4.y*v4.y + v4.z*v4.z + v4.w*v4.w;
    #pragma unroll
    for (int o = 16; o > 0; o >>= 1) {
        sum += __shfl_xor_sync(0xffffffffu, sum, o);
        sq  += __shfl_xor_sync(0xffffffffu, sq,  o);
    }
    if (lane == 0) { ws[wid] = sum; ws[8 + wid] = sq; }
    __syncthreads();
    float s8 = ws[lane & 7], q8 = ws[8 + (lane & 7)];
    #pragma unroll
    for (int o = 4; o > 0; o >>= 1) {
        s8 += __shfl_xor_sync(0xffffffffu, s8, o);
        q8 += __shfl_xor_sync(0xffffffffu, q8, o);
    }
    float m   = s8 * (1.f/1024.f);
    float inv = rsqrtf(q8 * (1.f/1024.f) - m * m + 1e-6f);
    float4 g0 = *(const float4*)(g + c0);
    float4 b0 = *(const float4*)(b + c0);
    float v[4];
    v[0]=(v4.x-m)*inv*g0.x+b0.x; v[1]=(v4.y-m)*inv*g0.y+b0.y;
    v[2]=(v4.z-m)*inv*g0.z+b0.z; v[3]=(v4.w-m)*inv*g0.w+b0.w;
    unsigned short h[4], l[4];
    #pragma unroll
    for (int q = 0; q < 4; q++) {
        h[q] = f2bf(v[q]);
        l[q] = f2bf(v[q] - bf2f(h[q]));
    }
    uint2 ph, pl;
    ph.x = h[0] | (h[1] << 16); ph.y = h[2] | (h[3] << 16);
    pl.x = l[0] | (l[1] << 16); pl.y = l[2] | (l[3] << 16);
    ((uint2*)(hi + rb))[t] = ph;
    ((uint2*)(lo + rb))[t] = pl;
}

// ---------------- convW: transpose W[K,N] -> [n][k] bf16 hi/lo ----------------
__global__ __launch_bounds__(256) void convW(const float* __restrict__ w,
                                             unsigned short* __restrict__ whi,
                                             unsigned short* __restrict__ wlo,
                                             int K, int N) {
    __shared__ float s[32][33];
    int t = threadIdx.x;
    int n0 = blockIdx.x * 32, k0 = blockIdx.y * 32;
    #pragma unroll
    for (int i = 0; i < 4; i++) {
        int idx = i * 256 + t;
        int kr = idx >> 5, nc = idx & 31;
        s[kr][nc] = w[(size_t)(k0 + kr) * N + n0 + nc];
    }
    __syncthreads();
    #pragma unroll
    for (int i = 0; i < 4; i++) {
        int idx = i * 256 + t;
        int nr = idx >> 5, kc = idx & 31;
        float v = s[kc][nr];
        unsigned short h = f2bf(v);
        size_t o = (size_t)(n0 + nr) * K + k0 + kc;
        whi[o] = h;
        wlo[o] = f2bf(v - bf2f(h));
    }
}

// ============ HMMA bf16 GEMM (pre-converted operands, cp.async pipeline) ======
#define PITCH 72
#define PLANE (128*PITCH)
#define BUFE  (4*PLANE)
#define GSMEM (2*BUFE*2)

__global__ __launch_bounds__(256) void gemm_bf(const unsigned short* __restrict__ Ahi,
                                               const unsigned short* __restrict__ Alo,
                                               const unsigned short* __restrict__ Bhi,
                                               const unsigned short* __restrict__ Blo,
                                               const float* __restrict__ bias,
                                               float* __restrict__ C,
                                               int M, int N, int K) {
    extern __shared__ unsigned short sm[];
    uint32_t sbase = smem_u32(sm);

    int t = threadIdx.x, wid = t >> 5, lane = t & 31;
    int wm = wid >> 2, wn = wid & 3;
    int bm = blockIdx.x * 128, bn = blockIdx.y * 128;
    int fr = lane >> 2, fc = lane & 3;

    int lr = t >> 1, lh = t & 1;
    const unsigned short* pA[2] = { Ahi + (size_t)(bm + lr) * K + lh * 32,
                                    Alo + (size_t)(bm + lr) * K + lh * 32 };
    const unsigned short* pB[2] = { Bhi + (size_t)(bn + lr) * K + lh * 32,
                                    Blo + (size_t)(bn + lr) * K + lh * 32 };
    uint32_t dbase = sbase + 2u * (uint32_t)(lr * PITCH + lh * 32);

    auto load_chunk = [&](int c, int buf) {
        uint32_t db = dbase + 2u * (uint32_t)(buf * BUFE);
        int ko = c * 64;
        #pragma unroll
        for (int pl = 0; pl < 2; pl++) {
            const char* sa = (const char*)(pA[pl] + ko);
            const char* sb = (const char*)(pB[pl] + ko);
            uint32_t da = db + 2u * (uint32_t)(pl * PLANE);
            uint32_t dbb = db + 2u * (uint32_t)((2 + pl) * PLANE);
            #pragma unroll
            for (int j = 0; j < 4; j++) {
                cp16(da  + j * 16, sa + j * 16);
                cp16(dbb + j * 16, sb + j * 16);
            }
        }
    };

    float acc[4][4][4] = {};

    int NC = K / 64;
    load_chunk(0, 0);
    CP_COMMIT();

    for (int c = 0; c < NC; c++) {
        int buf = c & 1;
        if (c + 1 < NC) {
            load_chunk(c + 1, buf ^ 1);
            CP_COMMIT();
            CP_WAIT(1);
        } else {
            CP_WAIT(0);
        }
        __syncthreads();

        const uint32_t* Ah = (const uint32_t*)(sm + buf * BUFE);
        const uint32_t* Al = (const uint32_t*)(sm + buf * BUFE + PLANE);
        const uint32_t* Bh = (const uint32_t*)(sm + buf * BUFE + 2 * PLANE);
        const uint32_t* Bl = (const uint32_t*)(sm + buf * BUFE + 3 * PLANE);
        #pragma unroll
        for (int ks = 0; ks < 4; ks++) {
            int kw = ks * 8;
            uint32_t ahi[4][4], alo[4][4], bhi[4][2], blo[4][2];
            #pragma unroll
            for (int mi = 0; mi < 4; mi++) {
                int r0 = (wm * 64 + mi * 16 + fr) * (PITCH/2) + kw + fc;
                int r1 = r0 + 8 * (PITCH/2);
                ahi[mi][0] = Ah[r0];     ahi[mi][1] = Ah[r1];
                ahi[mi][2] = Ah[r0 + 4]; ahi[mi][3] = Ah[r1 + 4];
                alo[mi][0] = Al[r0];     alo[mi][1] = Al[r1];
                alo[mi][2] = Al[r0 + 4]; alo[mi][3] = Al[r1 + 4];
            }
            #pragma unroll
            for (int ni = 0; ni < 4; ni++) {
                int n0 = (wn * 32 + ni * 8 + fr) * (PITCH/2) + kw + fc;
                bhi[ni][0] = Bh[n0]; bhi[ni][1] = Bh[n0 + 4];
                blo[ni][0] = Bl[n0]; blo[ni][1] = Bl[n0 + 4];
            }
            #pragma unroll
            for (int mi = 0; mi < 4; mi++)
                #pragma unroll
                for (int ni = 0; ni < 4; ni++) {
                    mma_bf16(acc[mi][ni], ahi[mi], bhi[ni]);
                    mma_bf16(acc[mi][ni], alo[mi], bhi[ni]);
                    mma_bf16(acc[mi][ni], ahi[mi], blo[ni]);
                }
        }
        __syncthreads();
    }

    #pragma unroll
    for (int mi = 0; mi < 4; mi++) {
        int row0 = bm + wm * 64 + mi * 16 + fr;
        #pragma unroll
        for (int ni = 0; ni < 4; ni++) {
            int col = bn + wn * 32 + ni * 8 + fc * 2;
            float2 bb = *(const float2*)(bias + col);
            float2 o0, o1;
            o0.x = leaky(acc[mi][ni][0] + bb.x);
            o0.y = leaky(acc[mi][ni][1] + bb.y);
            o1.x = leaky(acc[mi][ni][2] + bb.x);
            o1.y = leaky(acc[mi][ni][3] + bb.y);
            *(float2*)(C + (size_t)row0 * N + col)       = o0;
            *(float2*)(C + (size_t)(row0 + 8) * N + col) = o1;
        }
    }
}

// ---------------- full LayerNorm (output block, NF=2048) ----------------
template<int NF>
__global__ __launch_bounds__(256) void ln_kernel(const float* __restrict__ in,
                                                 float* __restrict__ out,
                                                 const float* __restrict__ g,
                                                 const float* __restrict__ b) {
    constexpr int VPT = NF / 256;
    __shared__ float ws[16];
    int t = threadIdx.x, wid = t >> 5, lane = t & 31;
    const float* row = in + (size_t)blockIdx.x * NF;
    float v[VPT];
    float sum = 0.f, sq = 0.f;
    #pragma unroll
    for (int i = 0; i < VPT; i++) {
        v[i] = row[threadIdx.x + i * 256];
        sum += v[i]; sq += v[i] * v[i];
    }
    #pragma unroll
    for (int o = 16; o > 0; o >>= 1) {
        sum += __shfl_xor_sync(0xffffffffu, sum, o);
        sq  += __shfl_xor_sync(0xffffffffu, sq,  o);
    }
    if (lane == 0) { ws[wid] = sum; ws[8 + wid] = sq; }
    __syncthreads();
    float s8 = ws[lane & 7], q8 = ws[8 + (lane & 7)];
    #pragma unroll
    for (int o = 4; o > 0; o >>= 1) {
        s8 += __shfl_xor_sync(0xffffffffu, s8, o);
        q8 += __shfl_xor_sync(0xffffffffu, q8, o);
    }
    float m   = s8 * (1.0f / NF);
    float inv = rsqrtf(q8 * (1.0f / NF) - m * m + 1e-6f);
    float* orow = out + (size_t)blockIdx.x * NF;
    #pragma unroll
    for (int i = 0; i < VPT; i++) {
        int c = threadIdx.x + i * 256;
        orow[c] = (v[i] - m) * inv * g[c] + b[c];
    }
}

// ---------------- fused LN2 + attention scorer ----------------
// Loads raw x2 (gemm2 output), applies LN2 in smem, writes normalized rows
// back to x (for pooling), then computes attention logits.
__global__ __launch_bounds__(256) void attn_kernel(float* __restrict__ x,
                                                   const float* __restrict__ g2,
                                                   const float* __restrict__ c2,
                                                   const float* __restrict__ w1,
                                                   const float* __restrict__ b1,
                                                   const float* __restrict__ lng,
                                                   const float* __restrict__ lnb,
                                                   const float* __restrict__ w2,
                                                   const float* __restrict__ b2,
                                                   const int*  __restrict__ mask,
                                                   float* __restrict__ att) {
    __shared__ float xs[32][256];
    __shared__ float t1[32][64];
    __shared__ float mrow[32], irow[32];
    int t  = threadIdx.x;
    int wid = t >> 5, lane = t & 31;
    int r0 = blockIdx.x * 32;

    const float4* xsrc = (const float4*)(x + (size_t)r0 * 256);
    float4* xdst = (float4*)&xs[0][0];
    #pragma unroll
    for (int i = 0; i < 8; i++) xdst[t + i * 256] = xsrc[t + i * 256];
    __syncthreads();

    // LN2 on the 32 staged rows: each warp handles 4 rows
    #pragma unroll
    for (int rr = 0; rr < 4; rr++) {
        int r = wid * 4 + rr;
        float s = 0.f, q = 0.f;
        #pragma unroll
        for (int k = lane; k < 256; k += 32) { float v = xs[r][k]; s += v; q += v * v; }
        #pragma unroll
        for (int o = 16; o > 0; o >>= 1) {
            s += __shfl_xor_sync(0xffffffffu, s, o);
            q += __shfl_xor_sync(0xffffffffu, q, o);
        }
        float m   = s * (1.f/256.f);
        float inv = rsqrtf(q * (1.f/256.f) - m * m + 1e-6f);
        #pragma unroll
        for (int k = lane; k < 256; k += 32) {
            float v = (xs[r][k] - m) * inv * g2[k] + c2[k];
            xs[r][k] = v;
            x[(size_t)(r0 + r) * 256 + k] = v;
        }
    }
    __syncthreads();

    #pragma unroll
    for (int o = 0; o < 8; o++) {
        int idx = o * 256 + t;
        int r = idx >> 6, c = idx & 63;
        float acc = b1[c];
        #pragma unroll 4
        for (int k = 0; k < 256; k++) acc += xs[r][k] * w1[k * 64 + c];
        t1[r][c] = leaky(acc);
    }
    __syncthreads();

    if (t < 32) {
        float s = 0.f, q = 0.f;
        #pragma unroll
        for (int k = 0; k < 64; k++) { float v = t1[t][k]; s += v; q += v * v; }
        float m = s * (1.f / 64.f), var = q * (1.f / 64.f) - m * m;
        mrow[t] = m; irow[t] = rsqrtf(var + 1e-6f);
    }
    __syncthreads();
    #pragma unroll
    for (int o = 0; o < 8; o++) {
        int idx = o * 256 + t;
        int r = idx >> 6, c = idx & 63;
        t1[r][c] = (t1[r][c] - mrow[r]) * irow[r] * lng[c] + lnb[c];
    }
    __syncthreads();

    int r = t >> 3, hd = t & 7;
    float acc = b2[hd];
    #pragma unroll
    for (int k = 0; k < 64; k++) acc += t1[r][k] * w2[k * 8 + hd];
    int gr = r0 + r;
    int b = gr >> 10, l = gr & 1023;
    if (mask[b * 1024 + l] == 0) acc = -1e9f;
    att[((size_t)b * NH_ + hd) * L_ + l] = acc;
}

// ---------------- softmax ----------------
__global__ __launch_bounds__(256) void softmax_kernel(float* __restrict__ att) {
    __shared__ float s[256];
    float* row = att + (size_t)blockIdx.x * L_;
    int t = threadIdx.x;
    float v[4]; float mx = -1e30f;
    #pragma unroll
    for (int i = 0; i < 4; i++) { v[i] = row[t + i * 256]; mx = fmaxf(mx, v[i]); }
    s[t] = mx; __syncthreads();
    for (int st = 128; st > 0; st >>= 1) { if (t < st) s[t] = fmaxf(s[t], s[t + st]); __syncthreads(); }
    mx = s[0]; __syncthreads();
    float sum = 0.f;
    #pragma unroll
    for (int i = 0; i < 4; i++) { v[i] = expf(v[i] - mx); sum += v[i]; }
    s[t] = sum; __syncthreads();
    for (int st = 128; st > 0; st >>= 1) { if (t < st) s[t] += s[t + st]; __syncthreads(); }
    float inv = 1.f / s[0];
    #pragma unroll
    for (int i = 0; i < 4; i++) row[t + i * 256] = v[i] * inv;
}

// ---------------- pooling ----------------
__global__ __launch_bounds__(256) void pool_partial(const float* __restrict__ x,
                                                    const float* __restrict__ att,
                                                    float* __restrict__ part) {
    int chunk = blockIdx.x, b = blockIdx.y;
    int t = threadIdx.x;
    __shared__ float as[8][64];
    int l0 = chunk * 64;
    for (int i = t; i < 512; i += 256) {
        int hd = i >> 6, l = i & 63;
        as[hd][l] = att[((size_t)b * NH_ + hd) * L_ + l0 + l];
    }
    __syncthreads();
    float acc[8] = {};
    for (int l = 0; l < 64; l++) {
        float xv = x[((size_t)b * L_ + l0 + l) * H_ + t];
        #pragma unroll
        for (int hd = 0; hd < 8; hd++) acc[hd] += as[hd][l] * xv;
    }
    #pragma unroll
    for (int hd = 0; hd < 8; hd++)
        part[(((size_t)b * 16 + chunk) * NH_ + hd) * H_ + t] = acc[hd];
}

__global__ __launch_bounds__(256) void pool_reduce(const float* __restrict__ part,
                                                   float* __restrict__ h) {
    int hd = blockIdx.x, b = blockIdx.y, t = threadIdx.x;
    float s = 0.f;
    #pragma unroll
    for (int c = 0; c < 16; c++)
        s += part[(((size_t)b * 16 + c) * NH_ + hd) * H_ + t];
    h[(size_t)b * OH_ + hd * H_ + t] = s;
}

// ---------------- M=8 output GEMM: split-K ----------------
__global__ __launch_bounds__(256) void out_partial(const float* __restrict__ h,
                                                   const float* __restrict__ w,
                                                   float* __restrict__ part, int N) {
    __shared__ float hs[8][128];
    int t = threadIdx.x;
    int j = blockIdx.x * 256 + t;
    int k0 = blockIdx.y * 128;
    for (int i = t; i < 1024; i += 256)
        hs[i >> 7][i & 127] = h[(size_t)(i >> 7) * OH_ + k0 + (i & 127)];
    __syncthreads();
    if (j >= N) return;
    float acc[8] = {};
    const float* wp = w + (size_t)k0 * N + j;
    #pragma unroll 8
    for (int kk = 0; kk < 128; kk++) {
        float wv = wp[(size_t)kk * N];
        #pragma unroll
        for (int b = 0; b < 8; b++) acc[b] += hs[b][kk] * wv;
    }
    float* pp = part + (size_t)(blockIdx.y * 8) * N + j;
    #pragma unroll
    for (int b = 0; b < 8; b++) pp[(size_t)b * N] = acc[b];
}

template<int MODE>
__global__ __launch_bounds__(256) void out_reduce(const float* __restrict__ part,
                                                  const float* __restrict__ bias,
                                                  float* __restrict__ o, int N) {
    int j = blockIdx.x * 256 + threadIdx.x;
    if (j >= N) return;
    float s[8] = {};
    #pragma unroll
    for (int ks = 0; ks < 16; ks++)
        #pragma unroll
        for (int b = 0; b < 8; b++)
            s[b] += part[(size_t)(ks * 8 + b) * N + j];
    float bb = bias[j];
    #pragma unroll
    for (int b = 0; b < 8; b++) {
        float v = s[b] + bb;
        o[(size_t)b * N + j] = MODE ? (1.f / (1.f + expf(-v))) : leaky(v);
    }
}

// ---------------- GO max-propagation (float2 CM scan) ----------------
__global__ __launch_bounds__(256) void maxprop_kernel(const float* __restrict__ p,
                                                      const float* __restrict__ CM,
                                                      float* __restrict__ out) {
    int i = blockIdx.x, t = threadIdx.x;
    __shared__ float red[256][9];
    float acc[8] = {};
    const float2* row2 = (const float2*)(CM + (size_t)i * LBL_);
    const int NJ2 = LBL_ / 2;   // 2383
    for (int j2 = t; j2 < NJ2; j2 += 256) {
        float2 c = row2[j2];
        if (c.x != 0.f) {
            int j = 2 * j2;
            #pragma unroll
            for (int b = 0; b < 8; b++)
                acc[b] = fmaxf(acc[b], p[(size_t)b * LBL_ + j] * c.x);
        }
        if (c.y != 0.f) {
            int j = 2 * j2 + 1;
            #pragma unroll
            for (int b = 0; b < 8; b++)
                acc[b] = fmaxf(acc[b], p[(size_t)b * LBL_ + j] * c.y);
        }
    }
    #pragma unroll
    for (int b = 0; b < 8; b++) red[t][b] = acc[b];
    __syncthreads();
    for (int s = 128; s > 0; s >>= 1) {
        if (t < s) {
            #pragma unroll
            for (int b = 0; b < 8; b++) red[t][b] = fmaxf(red[t][b], red[t + s][b]);
        }
        __syncthreads();
    }
    if (t < 8) out[(size_t)t * LBL_ + i] = red[0][t];
}

// ---------------- launch ----------------
extern "C" void kernel_launch(void* const* d_in, const int* in_sizes, int n_in,
                              void* d_out, int out_size) {
    const float* h_V   = (const float*)d_in[0];
    const int*   mask  = (const int*)  d_in[1];
    const float* ln0_g = (const float*)d_in[2];
    const float* ln0_b = (const float*)d_in[3];
    const float* w_in  = (const float*)d_in[4];
    const float* b_in  = (const float*)d_in[5];
    const float* ln1_g = (const float*)d_in[6];
    const float* ln1_b = (const float*)d_in[7];
    const float* w_h   = (const float*)d_in[8];
    const float* b_h   = (const float*)d_in[9];
    const float* ln2_g = (const float*)d_in[10];
    const float* ln2_b = (const float*)d_in[11];
    const float* a_w1  = (const float*)d_in[12];
    const float* a_b1  = (const float*)d_in[13];
    const float* a_lng = (const float*)d_in[14];
    const float* a_lnb = (const float*)d_in[15];
    const float* a_w2  = (const float*)d_in[16];
    const float* a_b2  = (const float*)d_in[17];
    const float* o_w1  = (const float*)d_in[18];
    const float* o_b1  = (const float*)d_in[19];
    const float* o_lng = (const float*)d_in[20];
    const float* o_lnb = (const float*)d_in[21];
    const float* o_w2  = (const float*)d_in[22];
    const float* o_b2  = (const float*)d_in[23];
    const float* CM    = (const float*)d_in[24];
    float* out = (float*)d_out;

    float *x1, *x2, *att, *part, *hb, *h1, *p, *op1, *op2;
    unsigned short *Ahi, *Alo, *Whi, *Wlo;
    cudaGetSymbolAddress((void**)&x1,    g_x1);
    cudaGetSymbolAddress((void**)&x2,    g_x2);
    cudaGetSymbolAddress((void**)&att,   g_att);
    cudaGetSymbolAddress((void**)&part,  g_part);
    cudaGetSymbolAddress((void**)&hb,    g_h);
    cudaGetSymbolAddress((void**)&h1,    g_h1);
    cudaGetSymbolAddress((void**)&p,     g_p);
    cudaGetSymbolAddress((void**)&op1,   g_op1);
    cudaGetSymbolAddress((void**)&op2,   g_op2);
    cudaGetSymbolAddress((void**)&Ahi,   g_Ahi);
    cudaGetSymbolAddress((void**)&Alo,   g_Alo);
    cudaGetSymbolAddress((void**)&Whi,   g_Whi);
    cudaGetSymbolAddress((void**)&Wlo,   g_Wlo);

    cudaFuncSetAttribute(gemm_bf, cudaFuncAttributeMaxDynamicSharedMemorySize, GSMEM);

    // input block
    convA1024<<<ROWS_, 256>>>(h_V, Ahi, Alo, ln0_g, ln0_b);
    convW<<<dim3(H_/32, F_/32), 256>>>(w_in, Whi, Wlo, F_, H_);
    gemm_bf<<<dim3(ROWS_/128, H_/128), 256, GSMEM>>>(Ahi, Alo, Whi, Wlo, b_in, x1,
                                                     ROWS_, H_, F_);
    // hidden block
    convA256<<<ROWS_/8, 256>>>(x1, Ahi, Alo, ln1_g, ln1_b);
    convW<<<dim3(H_/32, H_/32), 256>>>(w_h, Whi, Wlo, H_, H_);
    gemm_bf<<<dim3(ROWS_/128, H_/128), 256, GSMEM>>>(Ahi, Alo, Whi, Wlo, b_h, x2,
                                                     ROWS_, H_, H_);

    // attention pooling (LN2 fused into attn; attn writes normalized x2)
    attn_kernel<<<ROWS_/32, 256>>>(x2, ln2_g, ln2_b, a_w1, a_b1, a_lng, a_lnb,
                                   a_w2, a_b2, mask, att);
    softmax_kernel<<<B_*NH_, 256>>>(att);
    pool_partial<<<dim3(16, B_), 256>>>(x2, att, part);
    pool_reduce<<<dim3(NH_, B_), 256>>>(part, hb);

    // output block (split-K)
    out_partial<<<dim3(OH_/256, 16), 256>>>(hb, o_w1, op1, OH_);
    out_reduce<0><<<OH_/256, 256>>>(op1, o_b1, h1, OH_);
    ln_kernel<2048><<<B_, 256>>>(h1, h1, o_lng, o_lnb);
    out_partial<<<dim3((LBL_+255)/256, 16), 256>>>(h1, o_w2, op2, LBL_);
    out_reduce<1><<<(LBL_+255)/256, 256>>>(op2, o_b2, p, LBL_);

    // GO hierarchy max-product
    maxprop_kernel<<<LBL_, 256>>>(p, CM, out);
}